// round 14
// baseline (speedup 1.0000x reference)
#include <cuda_runtime.h>
#include <float.h>

#define NQ    16384
#define HID   128
#define PROP  64
#define SPACE 4
#define KNN   40
#define TJ    512            // candidate tile in smem (knn)
#define WPB   8              // warps per knn block
#define WQ    4              // queries per warp
#define CAP   128            // buffered candidates per query (smem)

// ---------------- scratch (device globals; no allocation allowed) ----------------
__device__ float g_t1[NQ * HID];
__device__ float g_t2[NQ * HID];
__device__ float g_xcat[NQ * 256];     // [x (128) | agg_mean (64) | agg_max (64)]
__device__ float g_xg[NQ * HID];
__device__ float g_s[NQ * SPACE];
__device__ float g_s2[NQ];
__device__ float g_h[NQ * PROP];
__device__ float g_kd[NQ * KNN];
__device__ int   g_kj[NQ * KNN];

// ---------------- generic fp32 GEMM, double-buffered ------------------------------
// C = act(A[M,Kd] @ W[Kd,Nd] + b). BM=64, BN=128, BK=16, 256 thr, tile 8x4.
__global__ __launch_bounds__(256) void gemm_kernel(
    const float* __restrict__ A, int lda,
    const float* __restrict__ W,          // row-major [Kd, Nd]
    const float* __restrict__ bias,
    float* __restrict__ C, int ldc,
    int Kd, int Nd, int relu)
{
    __shared__ float As[2][64][16];
    __shared__ float Bs[2][16][128];

    const int tid = threadIdx.x;
    const int m0  = blockIdx.x * 64;
    const int tn  = tid & 31;
    const int tm  = tid >> 5;
    const int arow = tid >> 2;
    const int ak   = (tid & 3) * 4;
    const int bn   = (tid & 31) * 4;
    const int bk   = tid >> 5;

    float acc[8][4];
#pragma unroll
    for (int i = 0; i < 8; i++)
#pragma unroll
        for (int j = 0; j < 4; j++) acc[i][j] = 0.f;

    float4 av, bv0, bv1;

#define GEMM_LDG(K0)                                                      \
    {                                                                     \
        const float* ap = A + (long)(m0 + arow) * lda + (K0) + ak;        \
        av.x = ((K0) + ak + 0 < Kd) ? ap[0] : 0.f;                        \
        av.y = ((K0) + ak + 1 < Kd) ? ap[1] : 0.f;                        \
        av.z = ((K0) + ak + 2 < Kd) ? ap[2] : 0.f;                        \
        av.w = ((K0) + ak + 3 < Kd) ? ap[3] : 0.f;                        \
        bv0 = make_float4(0.f, 0.f, 0.f, 0.f);                            \
        bv1 = make_float4(0.f, 0.f, 0.f, 0.f);                            \
        if ((K0) + bk < Kd) {                                             \
            const float* wp = W + (long)((K0) + bk) * Nd + bn;            \
            if (bn + 0 < Nd) bv0.x = wp[0];                               \
            if (bn + 1 < Nd) bv0.y = wp[1];                               \
            if (bn + 2 < Nd) bv0.z = wp[2];                               \
            if (bn + 3 < Nd) bv0.w = wp[3];                               \
        }                                                                 \
        if ((K0) + bk + 8 < Kd) {                                         \
            const float* wp = W + (long)((K0) + bk + 8) * Nd + bn;        \
            if (bn + 0 < Nd) bv1.x = wp[0];                               \
            if (bn + 1 < Nd) bv1.y = wp[1];                               \
            if (bn + 2 < Nd) bv1.z = wp[2];                               \
            if (bn + 3 < Nd) bv1.w = wp[3];                               \
        }                                                                 \
    }

#define GEMM_STS(BUF)                                                     \
    {                                                                     \
        *(float4*)&As[BUF][arow][ak]   = av;                              \
        *(float4*)&Bs[BUF][bk][bn]     = bv0;                             \
        *(float4*)&Bs[BUF][bk + 8][bn] = bv1;                             \
    }

    const int nT = (Kd + 15) / 16;
    GEMM_LDG(0);
    GEMM_STS(0);
    __syncthreads();

    for (int t = 0; t < nT; t++) {
        const int cur = t & 1;
        if (t + 1 < nT) GEMM_LDG((t + 1) * 16);

#pragma unroll
        for (int kk4 = 0; kk4 < 16; kk4 += 4) {
            float4 b0 = *(const float4*)&Bs[cur][kk4 + 0][tn * 4];
            float4 b1 = *(const float4*)&Bs[cur][kk4 + 1][tn * 4];
            float4 b2 = *(const float4*)&Bs[cur][kk4 + 2][tn * 4];
            float4 b3 = *(const float4*)&Bs[cur][kk4 + 3][tn * 4];
#pragma unroll
            for (int i = 0; i < 8; i++) {
                float4 a = *(const float4*)&As[cur][tm * 8 + i][kk4];
                acc[i][0] = fmaf(a.x, b0.x, acc[i][0]);
                acc[i][1] = fmaf(a.x, b0.y, acc[i][1]);
                acc[i][2] = fmaf(a.x, b0.z, acc[i][2]);
                acc[i][3] = fmaf(a.x, b0.w, acc[i][3]);
                acc[i][0] = fmaf(a.y, b1.x, acc[i][0]);
                acc[i][1] = fmaf(a.y, b1.y, acc[i][1]);
                acc[i][2] = fmaf(a.y, b1.z, acc[i][2]);
                acc[i][3] = fmaf(a.y, b1.w, acc[i][3]);
                acc[i][0] = fmaf(a.z, b2.x, acc[i][0]);
                acc[i][1] = fmaf(a.z, b2.y, acc[i][1]);
                acc[i][2] = fmaf(a.z, b2.z, acc[i][2]);
                acc[i][3] = fmaf(a.z, b2.w, acc[i][3]);
                acc[i][0] = fmaf(a.w, b3.x, acc[i][0]);
                acc[i][1] = fmaf(a.w, b3.y, acc[i][1]);
                acc[i][2] = fmaf(a.w, b3.z, acc[i][2]);
                acc[i][3] = fmaf(a.w, b3.w, acc[i][3]);
            }
        }

        if (t + 1 < nT) GEMM_STS(cur ^ 1);
        __syncthreads();
    }

#pragma unroll
    for (int i = 0; i < 8; i++) {
        int row = m0 + tm * 8 + i;
#pragma unroll
        for (int j = 0; j < 4; j++) {
            int col = tn * 4 + j;
            if (col < Nd) {
                float v = acc[i][j] + bias[col];
                if (relu) v = fmaxf(v, 0.f);
                C[(long)row * ldc + col] = v;
            }
        }
    }
}

// ------- thin GEMM (Nd=4), thread per row: y = A[:, :128](stride lda) @ W + b -----
__global__ __launch_bounds__(256) void thin_kernel(
    const float* __restrict__ A, int lda,
    const float* __restrict__ Wg,     // [128, 4]
    const float* __restrict__ bg,
    float4* __restrict__ y, float* __restrict__ s2)
{
    __shared__ float4 Ws[128];
    const int tid = threadIdx.x;
    if (tid < 128) Ws[tid] = ((const float4*)Wg)[tid];
    __syncthreads();

    const int row = blockIdx.x * 256 + tid;
    const float4* xr = (const float4*)(A + (long)row * lda);
    float4 acc = make_float4(bg[0], bg[1], bg[2], bg[3]);
#pragma unroll
    for (int k4 = 0; k4 < 32; k4++) {
        float4 xv = xr[k4];
        float4 w0 = Ws[k4 * 4 + 0];
        float4 w1 = Ws[k4 * 4 + 1];
        float4 w2 = Ws[k4 * 4 + 2];
        float4 w3 = Ws[k4 * 4 + 3];
        acc.x = fmaf(xv.x, w0.x, acc.x); acc.y = fmaf(xv.x, w0.y, acc.y);
        acc.z = fmaf(xv.x, w0.z, acc.z); acc.w = fmaf(xv.x, w0.w, acc.w);
        acc.x = fmaf(xv.y, w1.x, acc.x); acc.y = fmaf(xv.y, w1.y, acc.y);
        acc.z = fmaf(xv.y, w1.z, acc.z); acc.w = fmaf(xv.y, w1.w, acc.w);
        acc.x = fmaf(xv.z, w2.x, acc.x); acc.y = fmaf(xv.z, w2.y, acc.y);
        acc.z = fmaf(xv.z, w2.z, acc.z); acc.w = fmaf(xv.z, w2.w, acc.w);
        acc.x = fmaf(xv.w, w3.x, acc.x); acc.y = fmaf(xv.w, w3.y, acc.y);
        acc.z = fmaf(xv.w, w3.z, acc.z); acc.w = fmaf(xv.w, w3.w, acc.w);
    }
    y[row] = acc;
    if (s2) s2[row] = acc.x * acc.x + acc.y * acc.y + acc.z * acc.z + acc.w * acc.w;
}

// ---------------- kNN: values-only threshold list + buffered (e, j) append -------
// Sorted top-64 VALUES distributed 2/lane (rank r: lane r>>1, slot r&1, ascending).
// Accepted (e, j) pairs go to a per-query smem buffer in PARALLEL (ballot compact);
// exact top-40 recovered at the end by filtering the buffer with the final rank-39
// value. Compaction (keep v <= thr ==> shrinks to ~40) prevents overflow for any
// input order. e-space: e = d2 - s2i (monotone in d2).
__global__ __launch_bounds__(WPB * 32) void knn_kernel(
    const float4* __restrict__ s, const float* __restrict__ s2,
    float* __restrict__ kd, int* __restrict__ kj)
{
    __shared__ float4 sj[TJ];
    __shared__ float  s2j[TJ];
    __shared__ float2 kbuf[WPB * WQ * CAP];   // 32 KB

    const unsigned F = 0xffffffffu;
    const int tid  = threadIdx.x;
    const int lane = tid & 31;
    const int warp = tid >> 5;
    const int qb   = (blockIdx.x * WPB + warp) * WQ;
    const int r0   = 2 * lane;
    const int r1   = 2 * lane + 1;
    const unsigned below = (1u << lane) - 1u;

    float m2x[WQ], m2y[WQ], m2z[WQ], m2w[WQ], s2i[WQ];
    float q0v[WQ], q1v[WQ], thrE[WQ];
    int   cnt[WQ];

#pragma unroll
    for (int u = 0; u < WQ; u++) {
        float4 si = s[qb + u];
        s2i[u] = s2[qb + u];
        m2x[u] = -2.f * si.x; m2y[u] = -2.f * si.y;
        m2z[u] = -2.f * si.z; m2w[u] = -2.f * si.w;
        q0v[u] = FLT_MAX; q1v[u] = FLT_MAX;
        thrE[u] = FLT_MAX;
        cnt[u] = 0;
    }

// insert value v into the sorted 64-value list of query u
#define VINS(u, v)                                                        \
    {                                                                     \
        unsigned bb0 = __ballot_sync(F, q0v[u] < (v));                    \
        unsigned bb1 = __ballot_sync(F, q1v[u] < (v));                    \
        const int p = __popc(bb0) + __popc(bb1);                          \
        float sv = __shfl_up_sync(F, q1v[u], 1);                          \
        const float ov = q0v[u];                                          \
        if (r0 == p)      q0v[u] = (v);                                   \
        else if (r0 > p)  q0v[u] = sv;                                    \
        if (r1 == p)      q1v[u] = (v);                                   \
        else if (r1 > p)  q1v[u] = ov;                                    \
    }

    for (int t0 = 0; t0 < NQ; t0 += TJ) {
        __syncthreads();
        sj[tid]        = s[t0 + tid];
        sj[tid + 256]  = s[t0 + tid + 256];
        s2j[tid]       = s2[t0 + tid];
        s2j[tid + 256] = s2[t0 + tid + 256];
        __syncthreads();

        for (int g = 0; g < TJ / 64; g++) {
            const int ca = g * 64 + lane;
            const int jbase = t0 + g * 64;
            const float4 A4 = sj[ca];
            const float4 B4 = sj[ca + 32];
            const float  za = s2j[ca];
            const float  zb = s2j[ca + 32];
#pragma unroll
            for (int u = 0; u < WQ; u++) {
                float ea = fmaf(m2x[u], A4.x,
                           fmaf(m2y[u], A4.y,
                           fmaf(m2z[u], A4.z,
                           fmaf(m2w[u], A4.w, za))));
                float eb = fmaf(m2x[u], B4.x,
                           fmaf(m2y[u], B4.y,
                           fmaf(m2z[u], B4.z,
                           fmaf(m2w[u], B4.w, zb))));
                const float thr0 = thrE[u];
                unsigned hit = __ballot_sync(F, fminf(ea, eb) < thr0);
                if (hit) {
                    unsigned mA = __ballot_sync(F, ea < thr0);
                    unsigned mB = __ballot_sync(F, eb < thr0);
                    // serial: value-only threshold maintenance
                    unsigned m = mA;
                    while (m) {
                        const int src = __ffs(m) - 1; m &= m - 1;
                        const float v = __shfl_sync(F, ea, src);
                        VINS(u, v);
                    }
                    m = mB;
                    while (m) {
                        const int src = __ffs(m) - 1; m &= m - 1;
                        const float v = __shfl_sync(F, eb, src);
                        VINS(u, v);
                    }
                    thrE[u] = __shfl_sync(F, q1v[u], 19);   // rank 39
                    // parallel: append accepted (e, j) pairs to buffer
                    float2* bq = kbuf + (warp * WQ + u) * CAP;
                    int base = cnt[u];
                    if (ea < thr0)
                        bq[base + __popc(mA & below)] =
                            make_float2(ea, __int_as_float(jbase + lane));
                    base += __popc(mA);
                    if (eb < thr0)
                        bq[base + __popc(mB & below)] =
                            make_float2(eb, __int_as_float(jbase + 32 + lane));
                    cnt[u] = base + __popc(mB);
                    // compaction: keep v <= current thr (shrinks to ~40)
                    if (cnt[u] > CAP - 64) {
                        const float thv = thrE[u];
                        const int cn = cnt[u];
                        int nc = 0;
                        for (int b = 0; b < cn; b += 32) {
                            const int i = b + lane;
                            float2 ent = make_float2(FLT_MAX, 0.f);
                            if (i < cn) ent = bq[i];
                            const bool keep = ent.x <= thv;
                            unsigned mk = __ballot_sync(F, keep);
                            if (keep) bq[nc + __popc(mk & below)] = ent;
                            nc += __popc(mk);
                        }
                        cnt[u] = nc;
                    }
                }
            }
        }
    }

    // final: exact top-40 = buffer entries with v <= final rank-39 value
#pragma unroll
    for (int u = 0; u < WQ; u++) {
        const int q = qb + u;
        const float v39 = thrE[u];
        const float2* bq = kbuf + (warp * WQ + u) * CAP;
        const int cn = cnt[u];
        int outn = 0;
        for (int b = 0; b < cn; b += 32) {
            const int i = b + lane;
            float2 ent = make_float2(FLT_MAX, 0.f);
            if (i < cn) ent = bq[i];
            const bool keep = ent.x <= v39;
            unsigned mk = __ballot_sync(F, keep);
            const int pos = outn + __popc(mk & below);
            if (keep && pos < KNN) {
                kd[q * KNN + pos] = ent.x + s2i[u];
                kj[q * KNN + pos] = __float_as_int(ent.y);
            }
            outn += __popc(mk);
        }
    }
}

// ---------------- aggregate: warp per query, mean||max of h[idx]*w ---------------
__global__ void aggregate_kernel(
    const float* __restrict__ h, const float* __restrict__ kd,
    const int* __restrict__ kj, float* __restrict__ xcat)
{
    int gw   = (blockIdx.x * blockDim.x + threadIdx.x) >> 5;  // query
    int lane = threadIdx.x & 31;

    const float* dd = kd + gw * KNN;
    const int*   jj = kj + gw * KNN;

    float m0 = 0.f, m1 = 0.f;
    float x0 = -FLT_MAX, x1 = -FLT_MAX;
#pragma unroll
    for (int k = 0; k < KNN; k++) {
        int   j = jj[k];
        float w = expf(-10.f * fmaxf(dd[k], 0.f));
        float v0 = h[j * PROP + lane] * w;
        float v1 = h[j * PROP + 32 + lane] * w;
        m0 += v0; m1 += v1;
        x0 = fmaxf(x0, v0); x1 = fmaxf(x1, v1);
    }
    float* out = xcat + (long)gw * 256 + 128;
    const float inv = 1.f / (float)KNN;
    out[lane]      = m0 * inv;
    out[32 + lane] = m1 * inv;
    out[64 + lane] = x0;
    out[96 + lane] = x1;
}

// =================================================================================
extern "C" void kernel_launch(void* const* d_in, const int* in_sizes, int n_in,
                              void* d_out, int out_size)
{
    const float* x    = (const float*)d_in[0];
    const float* fc1W = (const float*)d_in[1];
    const float* fc1b = (const float*)d_in[2];
    const float* fc2W = (const float*)d_in[3];
    const float* fc2b = (const float*)d_in[4];
    const float* gsW  = (const float*)d_in[5];
    const float* gsb  = (const float*)d_in[6];
    const float* ghW  = (const float*)d_in[7];
    const float* ghb  = (const float*)d_in[8];
    const float* goW  = (const float*)d_in[9];
    const float* gob  = (const float*)d_in[10];
    const float* d1W  = (const float*)d_in[11];
    const float* d1b  = (const float*)d_in[12];
    const float* d2W  = (const float*)d_in[13];
    const float* d2b  = (const float*)d_in[14];
    const float* d3W  = (const float*)d_in[15];
    const float* d3b  = (const float*)d_in[16];
    const float* fc3W = (const float*)d_in[17];
    const float* fc3b = (const float*)d_in[18];
    const float* fc4W = (const float*)d_in[19];
    const float* fc4b = (const float*)d_in[20];
    float* out = (float*)d_out;

    float *t1, *t2, *xcat, *xg, *s, *s2n, *h, *kd;
    int *kj;
    cudaGetSymbolAddress((void**)&t1,   g_t1);
    cudaGetSymbolAddress((void**)&t2,   g_t2);
    cudaGetSymbolAddress((void**)&xcat, g_xcat);
    cudaGetSymbolAddress((void**)&xg,   g_xg);
    cudaGetSymbolAddress((void**)&s,    g_s);
    cudaGetSymbolAddress((void**)&s2n,  g_s2);
    cudaGetSymbolAddress((void**)&h,    g_h);
    cudaGetSymbolAddress((void**)&kd,   g_kd);
    cudaGetSymbolAddress((void**)&kj,   g_kj);

    const int GB = NQ / 64;  // gemm grid

    gemm_kernel<<<GB, 256>>>(x, 9, fc1W, fc1b, t1, HID, 9, HID, 1);          // my #1
    gemm_kernel<<<GB, 256>>>(t1, HID, fc2W, fc2b, xcat, 256, HID, HID, 1);   // my #2

    for (int l = 0; l < 4; l++) {
        thin_kernel<<<NQ / 256, 256>>>(xcat, 256, gsW + l * HID * SPACE,
                                       gsb + l * SPACE, (float4*)s, s2n);    // my #3
        knn_kernel<<<NQ / (WPB * WQ), WPB * 32>>>((const float4*)s, s2n, kd, kj); // my #4 (ncu)
        gemm_kernel<<<GB, 256>>>(xcat, 256, ghW + l * HID * PROP, ghb + l * PROP,
                                 h, PROP, HID, PROP, 0);
        aggregate_kernel<<<NQ / 8, 256>>>(h, kd, kj, xcat);
        gemm_kernel<<<GB, 256>>>(xcat, 256, goW + l * 256 * HID, gob + l * HID,
                                 xg, HID, 256, HID, 0);
        gemm_kernel<<<GB, 256>>>(xg, HID, d1W + l * HID * HID, d1b + l * HID,
                                 t1, HID, HID, HID, 1);
        gemm_kernel<<<GB, 256>>>(t1, HID, d2W + l * HID * HID, d2b + l * HID,
                                 t2, HID, HID, HID, 1);
        gemm_kernel<<<GB, 256>>>(t2, HID, d3W + l * HID * HID, d3b + l * HID,
                                 xcat, 256, HID, HID, 1);
    }

    gemm_kernel<<<GB, 256>>>(xcat, 256, fc3W, fc3b, t1, HID, HID, HID, 1);
    thin_kernel<<<NQ / 256, 256>>>(t1, HID, fc4W, fc4b, (float4*)out, nullptr);
}

// round 15
// speedup vs baseline: 1.0222x; 1.0222x over previous
#include <cuda_runtime.h>
#include <float.h>

#define NQ    16384
#define HID   128
#define PROP  64
#define SPACE 4
#define KNN   40
#define TJ    512            // candidate tile in smem (knn)
#define WPB   8              // warps per knn block
#define WQ    4              // queries per warp
#define CAP   176            // buffered candidates per query (smem)
#define TRIG  (CAP - 64)     // compaction trigger (max growth per group = 64)

// ---------------- scratch (device globals; no allocation allowed) ----------------
__device__ float g_t1[NQ * HID];
__device__ float g_t2[NQ * HID];
__device__ float g_xcat[NQ * 256];     // [x (128) | agg_mean (64) | agg_max (64)]
__device__ float g_xg[NQ * HID];
__device__ float g_s[NQ * SPACE];
__device__ float g_s2[NQ];
__device__ float g_h[NQ * PROP];
__device__ float g_kd[NQ * KNN];
__device__ int   g_kj[NQ * KNN];

// ---------------- generic fp32 GEMM, double-buffered ------------------------------
__global__ __launch_bounds__(256) void gemm_kernel(
    const float* __restrict__ A, int lda,
    const float* __restrict__ W,          // row-major [Kd, Nd]
    const float* __restrict__ bias,
    float* __restrict__ C, int ldc,
    int Kd, int Nd, int relu)
{
    __shared__ float As[2][64][16];
    __shared__ float Bs[2][16][128];

    const int tid = threadIdx.x;
    const int m0  = blockIdx.x * 64;
    const int tn  = tid & 31;
    const int tm  = tid >> 5;
    const int arow = tid >> 2;
    const int ak   = (tid & 3) * 4;
    const int bn   = (tid & 31) * 4;
    const int bk   = tid >> 5;

    float acc[8][4];
#pragma unroll
    for (int i = 0; i < 8; i++)
#pragma unroll
        for (int j = 0; j < 4; j++) acc[i][j] = 0.f;

    float4 av, bv0, bv1;

#define GEMM_LDG(K0)                                                      \
    {                                                                     \
        const float* ap = A + (long)(m0 + arow) * lda + (K0) + ak;        \
        av.x = ((K0) + ak + 0 < Kd) ? ap[0] : 0.f;                        \
        av.y = ((K0) + ak + 1 < Kd) ? ap[1] : 0.f;                        \
        av.z = ((K0) + ak + 2 < Kd) ? ap[2] : 0.f;                        \
        av.w = ((K0) + ak + 3 < Kd) ? ap[3] : 0.f;                        \
        bv0 = make_float4(0.f, 0.f, 0.f, 0.f);                            \
        bv1 = make_float4(0.f, 0.f, 0.f, 0.f);                            \
        if ((K0) + bk < Kd) {                                             \
            const float* wp = W + (long)((K0) + bk) * Nd + bn;            \
            if (bn + 0 < Nd) bv0.x = wp[0];                               \
            if (bn + 1 < Nd) bv0.y = wp[1];                               \
            if (bn + 2 < Nd) bv0.z = wp[2];                               \
            if (bn + 3 < Nd) bv0.w = wp[3];                               \
        }                                                                 \
        if ((K0) + bk + 8 < Kd) {                                         \
            const float* wp = W + (long)((K0) + bk + 8) * Nd + bn;        \
            if (bn + 0 < Nd) bv1.x = wp[0];                               \
            if (bn + 1 < Nd) bv1.y = wp[1];                               \
            if (bn + 2 < Nd) bv1.z = wp[2];                               \
            if (bn + 3 < Nd) bv1.w = wp[3];                               \
        }                                                                 \
    }

#define GEMM_STS(BUF)                                                     \
    {                                                                     \
        *(float4*)&As[BUF][arow][ak]   = av;                              \
        *(float4*)&Bs[BUF][bk][bn]     = bv0;                             \
        *(float4*)&Bs[BUF][bk + 8][bn] = bv1;                             \
    }

    const int nT = (Kd + 15) / 16;
    GEMM_LDG(0);
    GEMM_STS(0);
    __syncthreads();

    for (int t = 0; t < nT; t++) {
        const int cur = t & 1;
        if (t + 1 < nT) GEMM_LDG((t + 1) * 16);

#pragma unroll
        for (int kk4 = 0; kk4 < 16; kk4 += 4) {
            float4 b0 = *(const float4*)&Bs[cur][kk4 + 0][tn * 4];
            float4 b1 = *(const float4*)&Bs[cur][kk4 + 1][tn * 4];
            float4 b2 = *(const float4*)&Bs[cur][kk4 + 2][tn * 4];
            float4 b3 = *(const float4*)&Bs[cur][kk4 + 3][tn * 4];
#pragma unroll
            for (int i = 0; i < 8; i++) {
                float4 a = *(const float4*)&As[cur][tm * 8 + i][kk4];
                acc[i][0] = fmaf(a.x, b0.x, acc[i][0]);
                acc[i][1] = fmaf(a.x, b0.y, acc[i][1]);
                acc[i][2] = fmaf(a.x, b0.z, acc[i][2]);
                acc[i][3] = fmaf(a.x, b0.w, acc[i][3]);
                acc[i][0] = fmaf(a.y, b1.x, acc[i][0]);
                acc[i][1] = fmaf(a.y, b1.y, acc[i][1]);
                acc[i][2] = fmaf(a.y, b1.z, acc[i][2]);
                acc[i][3] = fmaf(a.y, b1.w, acc[i][3]);
                acc[i][0] = fmaf(a.z, b2.x, acc[i][0]);
                acc[i][1] = fmaf(a.z, b2.y, acc[i][1]);
                acc[i][2] = fmaf(a.z, b2.z, acc[i][2]);
                acc[i][3] = fmaf(a.z, b2.w, acc[i][3]);
                acc[i][0] = fmaf(a.w, b3.x, acc[i][0]);
                acc[i][1] = fmaf(a.w, b3.y, acc[i][1]);
                acc[i][2] = fmaf(a.w, b3.z, acc[i][2]);
                acc[i][3] = fmaf(a.w, b3.w, acc[i][3]);
            }
        }

        if (t + 1 < nT) GEMM_STS(cur ^ 1);
        __syncthreads();
    }

#pragma unroll
    for (int i = 0; i < 8; i++) {
        int row = m0 + tm * 8 + i;
#pragma unroll
        for (int j = 0; j < 4; j++) {
            int col = tn * 4 + j;
            if (col < Nd) {
                float v = acc[i][j] + bias[col];
                if (relu) v = fmaxf(v, 0.f);
                C[(long)row * ldc + col] = v;
            }
        }
    }
}

// ------- thin GEMM (Nd=4), thread per row: y = A[:, :128](stride lda) @ W + b -----
__global__ __launch_bounds__(256) void thin_kernel(
    const float* __restrict__ A, int lda,
    const float* __restrict__ Wg,     // [128, 4]
    const float* __restrict__ bg,
    float4* __restrict__ y, float* __restrict__ s2)
{
    __shared__ float4 Ws[128];
    const int tid = threadIdx.x;
    if (tid < 128) Ws[tid] = ((const float4*)Wg)[tid];
    __syncthreads();

    const int row = blockIdx.x * 256 + tid;
    const float4* xr = (const float4*)(A + (long)row * lda);
    float4 acc = make_float4(bg[0], bg[1], bg[2], bg[3]);
#pragma unroll
    for (int k4 = 0; k4 < 32; k4++) {
        float4 xv = xr[k4];
        float4 w0 = Ws[k4 * 4 + 0];
        float4 w1 = Ws[k4 * 4 + 1];
        float4 w2 = Ws[k4 * 4 + 2];
        float4 w3 = Ws[k4 * 4 + 3];
        acc.x = fmaf(xv.x, w0.x, acc.x); acc.y = fmaf(xv.x, w0.y, acc.y);
        acc.z = fmaf(xv.x, w0.z, acc.z); acc.w = fmaf(xv.x, w0.w, acc.w);
        acc.x = fmaf(xv.y, w1.x, acc.x); acc.y = fmaf(xv.y, w1.y, acc.y);
        acc.z = fmaf(xv.y, w1.z, acc.z); acc.w = fmaf(xv.y, w1.w, acc.w);
        acc.x = fmaf(xv.z, w2.x, acc.x); acc.y = fmaf(xv.z, w2.y, acc.y);
        acc.z = fmaf(xv.z, w2.z, acc.z); acc.w = fmaf(xv.z, w2.w, acc.w);
        acc.x = fmaf(xv.w, w3.x, acc.x); acc.y = fmaf(xv.w, w3.y, acc.y);
        acc.z = fmaf(xv.w, w3.z, acc.z); acc.w = fmaf(xv.w, w3.w, acc.w);
    }
    y[row] = acc;
    if (s2) s2[row] = acc.x * acc.x + acc.y * acc.y + acc.z * acc.z + acc.w * acc.w;
}

// ---------------- kNN helpers ----------------------------------------------------
// Bitonic sort of 256 values distributed 8/lane, gi = lane*8 + r, ascending.
__device__ __forceinline__ void sort256(float v[8], int lane)
{
    const unsigned F = 0xffffffffu;
#pragma unroll
    for (int k = 2; k <= 256; k <<= 1) {
#pragma unroll
        for (int j = k >> 1; j > 0; j >>= 1) {
            if (j >= 8) {
                const int dl = j >> 3;                         // lane distance
                const bool upper = (lane & dl) != 0;           // gi & j
                const bool asc   = (((lane << 3)) & k) == 0;   // gi & k (k>=16 here)
                const bool keepMin = (!upper) == asc;
#pragma unroll
                for (int r = 0; r < 8; r++) {
                    float o = __shfl_xor_sync(F, v[r], dl);
                    v[r] = keepMin ? fminf(v[r], o) : fmaxf(v[r], o);
                }
            } else {
#pragma unroll
                for (int r = 0; r < 8; r++) {
                    if ((r & j) == 0) {
                        const int r2 = r | j;
                        const bool asc = (((lane << 3) + r) & k) == 0;
                        float lo = fminf(v[r], v[r2]);
                        float hi = fmaxf(v[r], v[r2]);
                        v[r]  = asc ? lo : hi;
                        v[r2] = asc ? hi : lo;
                    }
                }
            }
        }
    }
}

// Rank-39 (40th smallest) value of the first n (<= CAP <= 256) buffered entries.
__device__ __forceinline__ float rank39_of(const float2* bq, int n, int lane)
{
    const unsigned F = 0xffffffffu;
    float v[8];
    const float4* p4 = (const float4*)bq;   // one float4 = two (val, idx) entries
#pragma unroll
    for (int t = 0; t < 4; t++) {
        const int e0 = lane * 8 + 2 * t;
        float4 f = make_float4(FLT_MAX, 0.f, FLT_MAX, 0.f);
        if (e0 < n) f = p4[lane * 4 + t];
        v[2 * t]     = (e0     < n) ? f.x : FLT_MAX;
        v[2 * t + 1] = (e0 + 1 < n) ? f.z : FLT_MAX;
    }
    sort256(v, lane);
    return __shfl_sync(F, v[7], 4);         // gi = 4*8 + 7 = 39
}

// In-place filter: keep entries with value <= thv. Returns new count.
__device__ __forceinline__ int compact_buf(float2* bq, int n, float thv,
                                           int lane, unsigned below)
{
    const unsigned F = 0xffffffffu;
    int nc = 0;
    for (int b = 0; b < n; b += 32) {
        const int i = b + lane;
        float2 ent = make_float2(FLT_MAX, 0.f);
        if (i < n) ent = bq[i];
        const bool keep = ent.x <= thv;
        unsigned mk = __ballot_sync(F, keep);
        if (keep) bq[nc + __popc(mk & below)] = ent;
        nc += __popc(mk);
    }
    return nc;
}

// ---------------- kNN: lazy-threshold buffered selection --------------------------
// Scan appends accepted (e, j) pairs in parallel (no per-element serial insert).
// Threshold updated only at compaction: exact rank-39 of buffer via bitonic sort.
// Since thr >= true rank-39 at all times, every true top-40 element is accepted
// and never dropped; final sort+filter yields the exact set. e = d2 - s2i.
__global__ __launch_bounds__(WPB * 32) void knn_kernel(
    const float4* __restrict__ s, const float* __restrict__ s2,
    float* __restrict__ kd, int* __restrict__ kj)
{
    extern __shared__ char dsm[];
    float4* sj   = (float4*)dsm;                               // TJ
    float*  s2j  = (float*)(dsm + TJ * 16);                    // TJ
    float2* kbuf = (float2*)(dsm + TJ * 16 + TJ * 4);          // 32 * CAP

    const unsigned F = 0xffffffffu;
    const int tid  = threadIdx.x;
    const int lane = tid & 31;
    const int warp = tid >> 5;
    const int qb   = (blockIdx.x * WPB + warp) * WQ;
    const unsigned below = (1u << lane) - 1u;

    float m2x[WQ], m2y[WQ], m2z[WQ], m2w[WQ], s2i[WQ], thr[WQ];
    int   cnt[WQ];

#pragma unroll
    for (int u = 0; u < WQ; u++) {
        float4 si = s[qb + u];
        s2i[u] = s2[qb + u];
        m2x[u] = -2.f * si.x; m2y[u] = -2.f * si.y;
        m2z[u] = -2.f * si.z; m2w[u] = -2.f * si.w;
        thr[u] = FLT_MAX;
        cnt[u] = 0;
    }

    for (int t0 = 0; t0 < NQ; t0 += TJ) {
        __syncthreads();
        sj[tid]        = s[t0 + tid];
        sj[tid + 256]  = s[t0 + tid + 256];
        s2j[tid]       = s2[t0 + tid];
        s2j[tid + 256] = s2[t0 + tid + 256];
        __syncthreads();

        for (int g = 0; g < TJ / 64; g++) {
            const int ca = g * 64 + lane;
            const int jbase = t0 + g * 64;
            const float4 A4 = sj[ca];
            const float4 B4 = sj[ca + 32];
            const float  za = s2j[ca];
            const float  zb = s2j[ca + 32];

            float ea[WQ], eb[WQ];
            bool  h[WQ];
#pragma unroll
            for (int u = 0; u < WQ; u++) {
                ea[u] = fmaf(m2x[u], A4.x,
                        fmaf(m2y[u], A4.y,
                        fmaf(m2z[u], A4.z,
                        fmaf(m2w[u], A4.w, za))));
                eb[u] = fmaf(m2x[u], B4.x,
                        fmaf(m2y[u], B4.y,
                        fmaf(m2z[u], B4.z,
                        fmaf(m2w[u], B4.w, zb))));
                h[u] = fminf(ea[u], eb[u]) < thr[u];
            }
            const unsigned any =
                __ballot_sync(F, (h[0] | h[1]) | (h[2] | h[3]));
            if (any) {
#pragma unroll
                for (int u = 0; u < WQ; u++) {
                    const float t = thr[u];
                    unsigned mA = __ballot_sync(F, ea[u] < t);
                    unsigned mB = __ballot_sync(F, eb[u] < t);
                    if (mA | mB) {
                        float2* bq = kbuf + (warp * WQ + u) * CAP;
                        int base = cnt[u];
                        if (ea[u] < t)
                            bq[base + __popc(mA & below)] =
                                make_float2(ea[u], __int_as_float(jbase + lane));
                        base += __popc(mA);
                        if (eb[u] < t)
                            bq[base + __popc(mB & below)] =
                                make_float2(eb[u], __int_as_float(jbase + 32 + lane));
                        cnt[u] = base + __popc(mB);
                        if (cnt[u] > TRIG) {
                            const float v39 = rank39_of(bq, cnt[u], lane);
                            thr[u] = v39;
                            cnt[u] = compact_buf(bq, cnt[u], v39, lane, below);
                        }
                    }
                }
            }
        }
    }

    // final: exact top-40 = buffer entries <= final rank-39 value
#pragma unroll
    for (int u = 0; u < WQ; u++) {
        const int q = qb + u;
        float2* bq = kbuf + (warp * WQ + u) * CAP;
        const int n = cnt[u];
        const float v39 = rank39_of(bq, n, lane);
        int outn = 0;
        for (int b = 0; b < n; b += 32) {
            const int i = b + lane;
            float2 ent = make_float2(FLT_MAX, 0.f);
            if (i < n) ent = bq[i];
            const bool keep = ent.x <= v39;
            unsigned mk = __ballot_sync(F, keep);
            const int pos = outn + __popc(mk & below);
            if (keep && pos < KNN) {
                kd[q * KNN + pos] = ent.x + s2i[u];
                kj[q * KNN + pos] = __float_as_int(ent.y);
            }
            outn += __popc(mk);
        }
    }
}

// ---------------- aggregate: warp per query, mean||max of h[idx]*w ---------------
__global__ void aggregate_kernel(
    const float* __restrict__ h, const float* __restrict__ kd,
    const int* __restrict__ kj, float* __restrict__ xcat)
{
    int gw   = (blockIdx.x * blockDim.x + threadIdx.x) >> 5;  // query
    int lane = threadIdx.x & 31;

    const float* dd = kd + gw * KNN;
    const int*   jj = kj + gw * KNN;

    float m0 = 0.f, m1 = 0.f;
    float x0 = -FLT_MAX, x1 = -FLT_MAX;
#pragma unroll
    for (int k = 0; k < KNN; k++) {
        int   j = jj[k];
        float w = expf(-10.f * fmaxf(dd[k], 0.f));
        float v0 = h[j * PROP + lane] * w;
        float v1 = h[j * PROP + 32 + lane] * w;
        m0 += v0; m1 += v1;
        x0 = fmaxf(x0, v0); x1 = fmaxf(x1, v1);
    }
    float* out = xcat + (long)gw * 256 + 128;
    const float inv = 1.f / (float)KNN;
    out[lane]      = m0 * inv;
    out[32 + lane] = m1 * inv;
    out[64 + lane] = x0;
    out[96 + lane] = x1;
}

// =================================================================================
extern "C" void kernel_launch(void* const* d_in, const int* in_sizes, int n_in,
                              void* d_out, int out_size)
{
    const float* x    = (const float*)d_in[0];
    const float* fc1W = (const float*)d_in[1];
    const float* fc1b = (const float*)d_in[2];
    const float* fc2W = (const float*)d_in[3];
    const float* fc2b = (const float*)d_in[4];
    const float* gsW  = (const float*)d_in[5];
    const float* gsb  = (const float*)d_in[6];
    const float* ghW  = (const float*)d_in[7];
    const float* ghb  = (const float*)d_in[8];
    const float* goW  = (const float*)d_in[9];
    const float* gob  = (const float*)d_in[10];
    const float* d1W  = (const float*)d_in[11];
    const float* d1b  = (const float*)d_in[12];
    const float* d2W  = (const float*)d_in[13];
    const float* d2b  = (const float*)d_in[14];
    const float* d3W  = (const float*)d_in[15];
    const float* d3b  = (const float*)d_in[16];
    const float* fc3W = (const float*)d_in[17];
    const float* fc3b = (const float*)d_in[18];
    const float* fc4W = (const float*)d_in[19];
    const float* fc4b = (const float*)d_in[20];
    float* out = (float*)d_out;

    float *t1, *t2, *xcat, *xg, *s, *s2n, *h, *kd;
    int *kj;
    cudaGetSymbolAddress((void**)&t1,   g_t1);
    cudaGetSymbolAddress((void**)&t2,   g_t2);
    cudaGetSymbolAddress((void**)&xcat, g_xcat);
    cudaGetSymbolAddress((void**)&xg,   g_xg);
    cudaGetSymbolAddress((void**)&s,    g_s);
    cudaGetSymbolAddress((void**)&s2n,  g_s2);
    cudaGetSymbolAddress((void**)&h,    g_h);
    cudaGetSymbolAddress((void**)&kd,   g_kd);
    cudaGetSymbolAddress((void**)&kj,   g_kj);

    const int GB = NQ / 64;  // gemm grid
    const int KNN_SMEM = TJ * 16 + TJ * 4 + WPB * WQ * CAP * (int)sizeof(float2);
    cudaFuncSetAttribute(knn_kernel,
                         cudaFuncAttributeMaxDynamicSharedMemorySize, KNN_SMEM);

    gemm_kernel<<<GB, 256>>>(x, 9, fc1W, fc1b, t1, HID, 9, HID, 1);          // my #1
    gemm_kernel<<<GB, 256>>>(t1, HID, fc2W, fc2b, xcat, 256, HID, HID, 1);   // my #2

    for (int l = 0; l < 4; l++) {
        thin_kernel<<<NQ / 256, 256>>>(xcat, 256, gsW + l * HID * SPACE,
                                       gsb + l * SPACE, (float4*)s, s2n);    // my #3
        knn_kernel<<<NQ / (WPB * WQ), WPB * 32, KNN_SMEM>>>(
            (const float4*)s, s2n, kd, kj);                                  // my #4 (ncu)
        gemm_kernel<<<GB, 256>>>(xcat, 256, ghW + l * HID * PROP, ghb + l * PROP,
                                 h, PROP, HID, PROP, 0);
        aggregate_kernel<<<NQ / 8, 256>>>(h, kd, kj, xcat);
        gemm_kernel<<<GB, 256>>>(xcat, 256, goW + l * 256 * HID, gob + l * HID,
                                 xg, HID, 256, HID, 0);
        gemm_kernel<<<GB, 256>>>(xg, HID, d1W + l * HID * HID, d1b + l * HID,
                                 t1, HID, HID, HID, 1);
        gemm_kernel<<<GB, 256>>>(t1, HID, d2W + l * HID * HID, d2b + l * HID,
                                 t2, HID, HID, HID, 1);
        gemm_kernel<<<GB, 256>>>(t2, HID, d3W + l * HID * HID, d3b + l * HID,
                                 xcat, 256, HID, HID, 1);
    }

    gemm_kernel<<<GB, 256>>>(xcat, 256, fc3W, fc3b, t1, HID, HID, HID, 1);
    thin_kernel<<<NQ / 256, 256>>>(t1, HID, fc4W, fc4b, (float4*)out, nullptr);
}

// round 16
// speedup vs baseline: 1.1070x; 1.0830x over previous
#include <cuda_runtime.h>
#include <float.h>

#define NQ    16384
#define HID   128
#define PROP  64
#define SPACE 4
#define KNN   40
#define TJ    512            // candidate tile in smem (knn)
#define WPB   8              // warps per knn block
#define WQ    2              // queries per warp
#define CAP   176            // buffered candidates per query (smem)
#define TRIG  (CAP - 64)     // compaction trigger (max growth per group = 64)

// ---------------- scratch (device globals; no allocation allowed) ----------------
__device__ float g_t1[NQ * HID];
__device__ float g_t2[NQ * HID];
__device__ float g_xcat[NQ * 256];     // [x (128) | agg_mean (64) | agg_max (64)]
__device__ float g_xg[NQ * HID];
__device__ float g_s[NQ * SPACE];
__device__ float g_s2[NQ];
__device__ float g_h[NQ * PROP];
__device__ float g_kd[NQ * KNN];
__device__ int   g_kj[NQ * KNN];

// ---------------- generic fp32 GEMM, double-buffered ------------------------------
__global__ __launch_bounds__(256) void gemm_kernel(
    const float* __restrict__ A, int lda,
    const float* __restrict__ W,          // row-major [Kd, Nd]
    const float* __restrict__ bias,
    float* __restrict__ C, int ldc,
    int Kd, int Nd, int relu)
{
    __shared__ float As[2][64][16];
    __shared__ float Bs[2][16][128];

    const int tid = threadIdx.x;
    const int m0  = blockIdx.x * 64;
    const int tn  = tid & 31;
    const int tm  = tid >> 5;
    const int arow = tid >> 2;
    const int ak   = (tid & 3) * 4;
    const int bn   = (tid & 31) * 4;
    const int bk   = tid >> 5;

    float acc[8][4];
#pragma unroll
    for (int i = 0; i < 8; i++)
#pragma unroll
        for (int j = 0; j < 4; j++) acc[i][j] = 0.f;

    float4 av, bv0, bv1;

#define GEMM_LDG(K0)                                                      \
    {                                                                     \
        const float* ap = A + (long)(m0 + arow) * lda + (K0) + ak;        \
        av.x = ((K0) + ak + 0 < Kd) ? ap[0] : 0.f;                        \
        av.y = ((K0) + ak + 1 < Kd) ? ap[1] : 0.f;                        \
        av.z = ((K0) + ak + 2 < Kd) ? ap[2] : 0.f;                        \
        av.w = ((K0) + ak + 3 < Kd) ? ap[3] : 0.f;                        \
        bv0 = make_float4(0.f, 0.f, 0.f, 0.f);                            \
        bv1 = make_float4(0.f, 0.f, 0.f, 0.f);                            \
        if ((K0) + bk < Kd) {                                             \
            const float* wp = W + (long)((K0) + bk) * Nd + bn;            \
            if (bn + 0 < Nd) bv0.x = wp[0];                               \
            if (bn + 1 < Nd) bv0.y = wp[1];                               \
            if (bn + 2 < Nd) bv0.z = wp[2];                               \
            if (bn + 3 < Nd) bv0.w = wp[3];                               \
        }                                                                 \
        if ((K0) + bk + 8 < Kd) {                                         \
            const float* wp = W + (long)((K0) + bk + 8) * Nd + bn;        \
            if (bn + 0 < Nd) bv1.x = wp[0];                               \
            if (bn + 1 < Nd) bv1.y = wp[1];                               \
            if (bn + 2 < Nd) bv1.z = wp[2];                               \
            if (bn + 3 < Nd) bv1.w = wp[3];                               \
        }                                                                 \
    }

#define GEMM_STS(BUF)                                                     \
    {                                                                     \
        *(float4*)&As[BUF][arow][ak]   = av;                              \
        *(float4*)&Bs[BUF][bk][bn]     = bv0;                             \
        *(float4*)&Bs[BUF][bk + 8][bn] = bv1;                             \
    }

    const int nT = (Kd + 15) / 16;
    GEMM_LDG(0);
    GEMM_STS(0);
    __syncthreads();

    for (int t = 0; t < nT; t++) {
        const int cur = t & 1;
        if (t + 1 < nT) GEMM_LDG((t + 1) * 16);

#pragma unroll
        for (int kk4 = 0; kk4 < 16; kk4 += 4) {
            float4 b0 = *(const float4*)&Bs[cur][kk4 + 0][tn * 4];
            float4 b1 = *(const float4*)&Bs[cur][kk4 + 1][tn * 4];
            float4 b2 = *(const float4*)&Bs[cur][kk4 + 2][tn * 4];
            float4 b3 = *(const float4*)&Bs[cur][kk4 + 3][tn * 4];
#pragma unroll
            for (int i = 0; i < 8; i++) {
                float4 a = *(const float4*)&As[cur][tm * 8 + i][kk4];
                acc[i][0] = fmaf(a.x, b0.x, acc[i][0]);
                acc[i][1] = fmaf(a.x, b0.y, acc[i][1]);
                acc[i][2] = fmaf(a.x, b0.z, acc[i][2]);
                acc[i][3] = fmaf(a.x, b0.w, acc[i][3]);
                acc[i][0] = fmaf(a.y, b1.x, acc[i][0]);
                acc[i][1] = fmaf(a.y, b1.y, acc[i][1]);
                acc[i][2] = fmaf(a.y, b1.z, acc[i][2]);
                acc[i][3] = fmaf(a.y, b1.w, acc[i][3]);
                acc[i][0] = fmaf(a.z, b2.x, acc[i][0]);
                acc[i][1] = fmaf(a.z, b2.y, acc[i][1]);
                acc[i][2] = fmaf(a.z, b2.z, acc[i][2]);
                acc[i][3] = fmaf(a.z, b2.w, acc[i][3]);
                acc[i][0] = fmaf(a.w, b3.x, acc[i][0]);
                acc[i][1] = fmaf(a.w, b3.y, acc[i][1]);
                acc[i][2] = fmaf(a.w, b3.z, acc[i][2]);
                acc[i][3] = fmaf(a.w, b3.w, acc[i][3]);
            }
        }

        if (t + 1 < nT) GEMM_STS(cur ^ 1);
        __syncthreads();
    }

#pragma unroll
    for (int i = 0; i < 8; i++) {
        int row = m0 + tm * 8 + i;
#pragma unroll
        for (int j = 0; j < 4; j++) {
            int col = tn * 4 + j;
            if (col < Nd) {
                float v = acc[i][j] + bias[col];
                if (relu) v = fmaxf(v, 0.f);
                C[(long)row * ldc + col] = v;
            }
        }
    }
}

// ------- thin GEMM (Nd=4), thread per row: y = A[:, :128](stride lda) @ W + b -----
__global__ __launch_bounds__(256) void thin_kernel(
    const float* __restrict__ A, int lda,
    const float* __restrict__ Wg,     // [128, 4]
    const float* __restrict__ bg,
    float4* __restrict__ y, float* __restrict__ s2)
{
    __shared__ float4 Ws[128];
    const int tid = threadIdx.x;
    if (tid < 128) Ws[tid] = ((const float4*)Wg)[tid];
    __syncthreads();

    const int row = blockIdx.x * 256 + tid;
    const float4* xr = (const float4*)(A + (long)row * lda);
    float4 acc = make_float4(bg[0], bg[1], bg[2], bg[3]);
#pragma unroll
    for (int k4 = 0; k4 < 32; k4++) {
        float4 xv = xr[k4];
        float4 w0 = Ws[k4 * 4 + 0];
        float4 w1 = Ws[k4 * 4 + 1];
        float4 w2 = Ws[k4 * 4 + 2];
        float4 w3 = Ws[k4 * 4 + 3];
        acc.x = fmaf(xv.x, w0.x, acc.x); acc.y = fmaf(xv.x, w0.y, acc.y);
        acc.z = fmaf(xv.x, w0.z, acc.z); acc.w = fmaf(xv.x, w0.w, acc.w);
        acc.x = fmaf(xv.y, w1.x, acc.x); acc.y = fmaf(xv.y, w1.y, acc.y);
        acc.z = fmaf(xv.y, w1.z, acc.z); acc.w = fmaf(xv.y, w1.w, acc.w);
        acc.x = fmaf(xv.z, w2.x, acc.x); acc.y = fmaf(xv.z, w2.y, acc.y);
        acc.z = fmaf(xv.z, w2.z, acc.z); acc.w = fmaf(xv.z, w2.w, acc.w);
        acc.x = fmaf(xv.w, w3.x, acc.x); acc.y = fmaf(xv.w, w3.y, acc.y);
        acc.z = fmaf(xv.w, w3.z, acc.z); acc.w = fmaf(xv.w, w3.w, acc.w);
    }
    y[row] = acc;
    if (s2) s2[row] = acc.x * acc.x + acc.y * acc.y + acc.z * acc.z + acc.w * acc.w;
}

// ---------------- kNN helpers ----------------------------------------------------
// Bitonic sort of 256 values distributed 8/lane, gi = lane*8 + r, ascending.
__device__ __forceinline__ void sort256(float v[8], int lane)
{
    const unsigned F = 0xffffffffu;
#pragma unroll
    for (int k = 2; k <= 256; k <<= 1) {
#pragma unroll
        for (int j = k >> 1; j > 0; j >>= 1) {
            if (j >= 8) {
                const int dl = j >> 3;                         // lane distance
                const bool upper = (lane & dl) != 0;           // gi & j
                const bool asc   = (((lane << 3)) & k) == 0;   // gi & k (k>=16 here)
                const bool keepMin = (!upper) == asc;
#pragma unroll
                for (int r = 0; r < 8; r++) {
                    float o = __shfl_xor_sync(F, v[r], dl);
                    v[r] = keepMin ? fminf(v[r], o) : fmaxf(v[r], o);
                }
            } else {
#pragma unroll
                for (int r = 0; r < 8; r++) {
                    if ((r & j) == 0) {
                        const int r2 = r | j;
                        const bool asc = (((lane << 3) + r) & k) == 0;
                        float lo = fminf(v[r], v[r2]);
                        float hi = fmaxf(v[r], v[r2]);
                        v[r]  = asc ? lo : hi;
                        v[r2] = asc ? hi : lo;
                    }
                }
            }
        }
    }
}

// Rank-39 (40th smallest) value of the first n (<= CAP <= 256) buffered entries.
__device__ __forceinline__ float rank39_of(const float2* bq, int n, int lane)
{
    const unsigned F = 0xffffffffu;
    float v[8];
    const float4* p4 = (const float4*)bq;   // one float4 = two (val, idx) entries
#pragma unroll
    for (int t = 0; t < 4; t++) {
        const int e0 = lane * 8 + 2 * t;
        float4 f = make_float4(FLT_MAX, 0.f, FLT_MAX, 0.f);
        if (e0 < n) f = p4[lane * 4 + t];
        v[2 * t]     = (e0     < n) ? f.x : FLT_MAX;
        v[2 * t + 1] = (e0 + 1 < n) ? f.z : FLT_MAX;
    }
    sort256(v, lane);
    return __shfl_sync(F, v[7], 4);         // gi = 4*8 + 7 = 39
}

// In-place filter: keep entries with value <= thv. Returns new count.
__device__ __forceinline__ int compact_buf(float2* bq, int n, float thv,
                                           int lane, unsigned below)
{
    const unsigned F = 0xffffffffu;
    int nc = 0;
    for (int b = 0; b < n; b += 32) {
        const int i = b + lane;
        float2 ent = make_float2(FLT_MAX, 0.f);
        if (i < n) ent = bq[i];
        const bool keep = ent.x <= thv;
        unsigned mk = __ballot_sync(F, keep);
        if (keep) bq[nc + __popc(mk & below)] = ent;
        nc += __popc(mk);
    }
    return nc;
}

// ---------------- kNN: lazy-threshold buffered selection, WQ=2 -------------------
// Scan appends accepted (e, j) pairs in parallel (no per-element serial insert).
// Threshold updated only at compaction: exact rank-39 of buffer via bitonic sort.
// thr >= true rank-39 at all times, so every true top-40 element is accepted and
// never dropped; final sort+filter yields the exact set. e = d2 - s2i.
__global__ __launch_bounds__(WPB * 32, 5) void knn_kernel(
    const float4* __restrict__ s, const float* __restrict__ s2,
    float* __restrict__ kd, int* __restrict__ kj)
{
    extern __shared__ char dsm[];
    float4* sj   = (float4*)dsm;                               // TJ
    float*  s2j  = (float*)(dsm + TJ * 16);                    // TJ
    float2* kbuf = (float2*)(dsm + TJ * 16 + TJ * 4);          // WPB*WQ*CAP

    const unsigned F = 0xffffffffu;
    const int tid  = threadIdx.x;
    const int lane = tid & 31;
    const int warp = tid >> 5;
    const int qb   = (blockIdx.x * WPB + warp) * WQ;
    const unsigned below = (1u << lane) - 1u;

    float m2x[WQ], m2y[WQ], m2z[WQ], m2w[WQ], s2i[WQ], thr[WQ];
    int   cnt[WQ];

#pragma unroll
    for (int u = 0; u < WQ; u++) {
        float4 si = s[qb + u];
        s2i[u] = s2[qb + u];
        m2x[u] = -2.f * si.x; m2y[u] = -2.f * si.y;
        m2z[u] = -2.f * si.z; m2w[u] = -2.f * si.w;
        thr[u] = FLT_MAX;
        cnt[u] = 0;
    }

    for (int t0 = 0; t0 < NQ; t0 += TJ) {
        __syncthreads();
        sj[tid]        = s[t0 + tid];
        sj[tid + 256]  = s[t0 + tid + 256];
        s2j[tid]       = s2[t0 + tid];
        s2j[tid + 256] = s2[t0 + tid + 256];
        __syncthreads();

        for (int g = 0; g < TJ / 64; g++) {
            const int ca = g * 64 + lane;
            const int jbase = t0 + g * 64;
            const float4 A4 = sj[ca];
            const float4 B4 = sj[ca + 32];
            const float  za = s2j[ca];
            const float  zb = s2j[ca + 32];

            float ea[WQ], eb[WQ];
            bool  h[WQ];
#pragma unroll
            for (int u = 0; u < WQ; u++) {
                ea[u] = fmaf(m2x[u], A4.x,
                        fmaf(m2y[u], A4.y,
                        fmaf(m2z[u], A4.z,
                        fmaf(m2w[u], A4.w, za))));
                eb[u] = fmaf(m2x[u], B4.x,
                        fmaf(m2y[u], B4.y,
                        fmaf(m2z[u], B4.z,
                        fmaf(m2w[u], B4.w, zb))));
                h[u] = fminf(ea[u], eb[u]) < thr[u];
            }
            const unsigned any = __ballot_sync(F, h[0] | h[1]);
            if (any) {
#pragma unroll
                for (int u = 0; u < WQ; u++) {
                    const float t = thr[u];
                    unsigned mA = __ballot_sync(F, ea[u] < t);
                    unsigned mB = __ballot_sync(F, eb[u] < t);
                    if (mA | mB) {
                        float2* bq = kbuf + (warp * WQ + u) * CAP;
                        int base = cnt[u];
                        if (ea[u] < t)
                            bq[base + __popc(mA & below)] =
                                make_float2(ea[u], __int_as_float(jbase + lane));
                        base += __popc(mA);
                        if (eb[u] < t)
                            bq[base + __popc(mB & below)] =
                                make_float2(eb[u], __int_as_float(jbase + 32 + lane));
                        cnt[u] = base + __popc(mB);
                        if (cnt[u] > TRIG) {
                            const float v39 = rank39_of(bq, cnt[u], lane);
                            thr[u] = v39;
                            cnt[u] = compact_buf(bq, cnt[u], v39, lane, below);
                        }
                    }
                }
            }
        }
    }

    // final: exact top-40 = buffer entries <= final rank-39 value
#pragma unroll
    for (int u = 0; u < WQ; u++) {
        const int q = qb + u;
        float2* bq = kbuf + (warp * WQ + u) * CAP;
        const int n = cnt[u];
        const float v39 = rank39_of(bq, n, lane);
        int outn = 0;
        for (int b = 0; b < n; b += 32) {
            const int i = b + lane;
            float2 ent = make_float2(FLT_MAX, 0.f);
            if (i < n) ent = bq[i];
            const bool keep = ent.x <= v39;
            unsigned mk = __ballot_sync(F, keep);
            const int pos = outn + __popc(mk & below);
            if (keep && pos < KNN) {
                kd[q * KNN + pos] = ent.x + s2i[u];
                kj[q * KNN + pos] = __float_as_int(ent.y);
            }
            outn += __popc(mk);
        }
    }
}

// ---------------- aggregate: warp per query, mean||max of h[idx]*w ---------------
__global__ void aggregate_kernel(
    const float* __restrict__ h, const float* __restrict__ kd,
    const int* __restrict__ kj, float* __restrict__ xcat)
{
    int gw   = (blockIdx.x * blockDim.x + threadIdx.x) >> 5;  // query
    int lane = threadIdx.x & 31;

    const float* dd = kd + gw * KNN;
    const int*   jj = kj + gw * KNN;

    float m0 = 0.f, m1 = 0.f;
    float x0 = -FLT_MAX, x1 = -FLT_MAX;
#pragma unroll
    for (int k = 0; k < KNN; k++) {
        int   j = jj[k];
        float w = expf(-10.f * fmaxf(dd[k], 0.f));
        float v0 = h[j * PROP + lane] * w;
        float v1 = h[j * PROP + 32 + lane] * w;
        m0 += v0; m1 += v1;
        x0 = fmaxf(x0, v0); x1 = fmaxf(x1, v1);
    }
    float* out = xcat + (long)gw * 256 + 128;
    const float inv = 1.f / (float)KNN;
    out[lane]      = m0 * inv;
    out[32 + lane] = m1 * inv;
    out[64 + lane] = x0;
    out[96 + lane] = x1;
}

// =================================================================================
extern "C" void kernel_launch(void* const* d_in, const int* in_sizes, int n_in,
                              void* d_out, int out_size)
{
    const float* x    = (const float*)d_in[0];
    const float* fc1W = (const float*)d_in[1];
    const float* fc1b = (const float*)d_in[2];
    const float* fc2W = (const float*)d_in[3];
    const float* fc2b = (const float*)d_in[4];
    const float* gsW  = (const float*)d_in[5];
    const float* gsb  = (const float*)d_in[6];
    const float* ghW  = (const float*)d_in[7];
    const float* ghb  = (const float*)d_in[8];
    const float* goW  = (const float*)d_in[9];
    const float* gob  = (const float*)d_in[10];
    const float* d1W  = (const float*)d_in[11];
    const float* d1b  = (const float*)d_in[12];
    const float* d2W  = (const float*)d_in[13];
    const float* d2b  = (const float*)d_in[14];
    const float* d3W  = (const float*)d_in[15];
    const float* d3b  = (const float*)d_in[16];
    const float* fc3W = (const float*)d_in[17];
    const float* fc3b = (const float*)d_in[18];
    const float* fc4W = (const float*)d_in[19];
    const float* fc4b = (const float*)d_in[20];
    float* out = (float*)d_out;

    float *t1, *t2, *xcat, *xg, *s, *s2n, *h, *kd;
    int *kj;
    cudaGetSymbolAddress((void**)&t1,   g_t1);
    cudaGetSymbolAddress((void**)&t2,   g_t2);
    cudaGetSymbolAddress((void**)&xcat, g_xcat);
    cudaGetSymbolAddress((void**)&xg,   g_xg);
    cudaGetSymbolAddress((void**)&s,    g_s);
    cudaGetSymbolAddress((void**)&s2n,  g_s2);
    cudaGetSymbolAddress((void**)&h,    g_h);
    cudaGetSymbolAddress((void**)&kd,   g_kd);
    cudaGetSymbolAddress((void**)&kj,   g_kj);

    const int GB = NQ / 64;  // gemm grid
    const int KNN_SMEM = TJ * 16 + TJ * 4 + WPB * WQ * CAP * (int)sizeof(float2);
    cudaFuncSetAttribute(knn_kernel,
                         cudaFuncAttributeMaxDynamicSharedMemorySize, KNN_SMEM);

    gemm_kernel<<<GB, 256>>>(x, 9, fc1W, fc1b, t1, HID, 9, HID, 1);          // my #1
    gemm_kernel<<<GB, 256>>>(t1, HID, fc2W, fc2b, xcat, 256, HID, HID, 1);   // my #2

    for (int l = 0; l < 4; l++) {
        thin_kernel<<<NQ / 256, 256>>>(xcat, 256, gsW + l * HID * SPACE,
                                       gsb + l * SPACE, (float4*)s, s2n);    // my #3
        knn_kernel<<<NQ / (WPB * WQ), WPB * 32, KNN_SMEM>>>(
            (const float4*)s, s2n, kd, kj);                                  // my #4 (ncu)
        gemm_kernel<<<GB, 256>>>(xcat, 256, ghW + l * HID * PROP, ghb + l * PROP,
                                 h, PROP, HID, PROP, 0);
        aggregate_kernel<<<NQ / 8, 256>>>(h, kd, kj, xcat);
        gemm_kernel<<<GB, 256>>>(xcat, 256, goW + l * 256 * HID, gob + l * HID,
                                 xg, HID, 256, HID, 0);
        gemm_kernel<<<GB, 256>>>(xg, HID, d1W + l * HID * HID, d1b + l * HID,
                                 t1, HID, HID, HID, 1);
        gemm_kernel<<<GB, 256>>>(t1, HID, d2W + l * HID * HID, d2b + l * HID,
                                 t2, HID, HID, HID, 1);
        gemm_kernel<<<GB, 256>>>(t2, HID, d3W + l * HID * HID, d3b + l * HID,
                                 xcat, 256, HID, HID, 1);
    }

    gemm_kernel<<<GB, 256>>>(xcat, 256, fc3W, fc3b, t1, HID, HID, HID, 1);
    thin_kernel<<<NQ / 256, 256>>>(t1, HID, fc4W, fc4b, (float4*)out, nullptr);
}